// round 2
// baseline (speedup 1.0000x reference)
#include <cuda_runtime.h>
#include <math.h>

#define N_NODES 50000
#define E_RAW   800000
#define ET      (E_RAW + N_NODES)
#define IN_F    256
#define HC      256      // HEADS * OUT_F
#define C_OUT   64
#define NEG_SLOPE 0.2f

// ---- scratch (static __device__ arrays; no runtime allocation) ----
__device__ float g_xl[N_NODES * HC];          // 51.2 MB
__device__ float g_xr[N_NODES * HC];          // 51.2 MB
__device__ float g_out[N_NODES * C_OUT];      // 12.8 MB
__device__ int   g_counts[N_NODES];
__device__ int   g_cursor[N_NODES];
__device__ int   g_offsets[N_NODES + 1];
__device__ int   g_src_sorted[ET];
__device__ float g_sum[C_OUT];
__device__ float g_sumsq[C_OUT];
__device__ float g_scale[C_OUT];
__device__ float g_shift[C_OUT];

// ---------------- zero scratch ----------------
__global__ void zero_kernel() {
    int i = blockIdx.x * blockDim.x + threadIdx.x;
    if (i < N_NODES) { g_counts[i] = 0; g_cursor[i] = 0; }
    if (i < C_OUT)   { g_sum[i] = 0.f; g_sumsq[i] = 0.f; }
}

// ---------------- fused GEMM: Y = X @ [Wl | Wr] ----------------
// C[50000,512] tiled 128x128x16, 256 threads, 8x8 micro-tile, fp32.
__global__ void gemm_kernel(const float* __restrict__ X,
                            const float* __restrict__ Wl,
                            const float* __restrict__ Wr) {
    const int BM = 128, BK = 16;
    __shared__ float As[BK][BM + 4];
    __shared__ float Bs[BK][128];

    int bx = blockIdx.x;               // 0..3 : col-block of the [.|.] 512 cols
    int by = blockIdx.y;
    const float* W = (bx < 2) ? Wl : Wr;
    float*       Y = (bx < 2) ? g_xl : g_xr;
    int colBase = (bx & 1) * 128;

    int tid = threadIdx.x;
    int tr = tid >> 4;                 // 0..15
    int tc = tid & 15;                 // 0..15

    float acc[8][8];
#pragma unroll
    for (int i = 0; i < 8; i++)
#pragma unroll
        for (int j = 0; j < 8; j++) acc[i][j] = 0.f;

    int arow = tid >> 2;               // 0..63
    int acol = (tid & 3) << 2;         // 0,4,8,12
    int brow = tid >> 5;               // 0..7
    int bcol = (tid & 31) << 2;        // 0..124
    int rowG = by * BM;

    for (int k0 = 0; k0 < IN_F; k0 += BK) {
#pragma unroll
        for (int r = 0; r < 2; r++) {
            int row = rowG + arow + r * 64;
            float4 v = make_float4(0.f, 0.f, 0.f, 0.f);
            if (row < N_NODES) v = *(const float4*)(X + (long)row * IN_F + k0 + acol);
            As[acol + 0][arow + r * 64] = v.x;
            As[acol + 1][arow + r * 64] = v.y;
            As[acol + 2][arow + r * 64] = v.z;
            As[acol + 3][arow + r * 64] = v.w;
        }
#pragma unroll
        for (int r = 0; r < 2; r++) {
            int kk = k0 + brow + r * 8;
            float4 v = *(const float4*)(W + (long)kk * HC + colBase + bcol);
            *(float4*)&Bs[brow + r * 8][bcol] = v;
        }
        __syncthreads();
#pragma unroll
        for (int kk = 0; kk < BK; kk++) {
            float a[8], b[8];
#pragma unroll
            for (int i = 0; i < 8; i++) a[i] = As[kk][tr * 8 + i];
#pragma unroll
            for (int j = 0; j < 8; j++) b[j] = Bs[kk][tc * 8 + j];
#pragma unroll
            for (int i = 0; i < 8; i++)
#pragma unroll
                for (int j = 0; j < 8; j++)
                    acc[i][j] = fmaf(a[i], b[j], acc[i][j]);
        }
        __syncthreads();
    }
#pragma unroll
    for (int i = 0; i < 8; i++) {
        int row = rowG + tr * 8 + i;
        if (row >= N_NODES) continue;
#pragma unroll
        for (int j = 0; j < 8; j += 4) {
            float4 v = make_float4(acc[i][j], acc[i][j + 1], acc[i][j + 2], acc[i][j + 3]);
            *(float4*)(Y + (long)row * HC + colBase + tc * 8 + j) = v;
        }
    }
}

// ---------------- CSR build (dst-sorted) ----------------
__global__ void hist_kernel(const int* __restrict__ E) {
    int i = blockIdx.x * blockDim.x + threadIdx.x;
    if (i >= ET) return;
    int d = (i < E_RAW) ? E[E_RAW + i] : (i - E_RAW);
    atomicAdd(&g_counts[d], 1);
}

__global__ void scan_kernel() {
    __shared__ int sh[1024];
    __shared__ int carry;
    int t = threadIdx.x;
    if (t == 0) { carry = 0; g_offsets[0] = 0; }
    __syncthreads();
    for (int base = 0; base < N_NODES; base += 1024) {
        int i = base + t;
        int v = (i < N_NODES) ? g_counts[i] : 0;
        sh[t] = v;
        __syncthreads();
        for (int off = 1; off < 1024; off <<= 1) {
            int add = (t >= off) ? sh[t - off] : 0;
            __syncthreads();
            sh[t] += add;
            __syncthreads();
        }
        if (i < N_NODES) g_offsets[i + 1] = carry + sh[t];
        __syncthreads();
        if (t == 0) carry += sh[1023];
        __syncthreads();
    }
}

__global__ void scatter_kernel(const int* __restrict__ E) {
    int i = blockIdx.x * blockDim.x + threadIdx.x;
    if (i >= ET) return;
    int s, d;
    if (i < E_RAW) { s = E[i]; d = E[E_RAW + i]; }
    else           { s = d = i - E_RAW; }
    int pos = atomicAdd(&g_cursor[d], 1);
    g_src_sorted[g_offsets[d] + pos] = s;
}

// ---------------- attention: one warp per destination node ----------------
// lane l owns channels [8l, 8l+8): head h = l>>3, output sub-range s = l&7.
__global__ void attn_kernel(const float* __restrict__ att,
                            const float* __restrict__ bias) {
    __shared__ float bsum[C_OUT];
    __shared__ float bsq[C_OUT];
    int tid = threadIdx.x;
    if (tid < C_OUT) { bsum[tid] = 0.f; bsq[tid] = 0.f; }
    __syncthreads();

    int warp = (blockIdx.x * blockDim.x + tid) >> 5;
    int lane = tid & 31;

    if (warp < N_NODES) {
        int dst = warp;
        const float4* xr4 = ((const float4*)g_xr) + (long)dst * 64 + lane * 2;
        float4 r0 = xr4[0], r1 = xr4[1];
        float xrv[8] = {r0.x, r0.y, r0.z, r0.w, r1.x, r1.y, r1.z, r1.w};
        float4 a0 = ((const float4*)att)[lane * 2];
        float4 a1 = ((const float4*)att)[lane * 2 + 1];
        float attv[8] = {a0.x, a0.y, a0.z, a0.w, a1.x, a1.y, a1.z, a1.w};

        float m = -1e30f, denom = 0.f;
        float acc[8] = {0.f, 0.f, 0.f, 0.f, 0.f, 0.f, 0.f, 0.f};

        int e0 = g_offsets[dst], e1 = g_offsets[dst + 1];
        for (int e = e0; e < e1; e++) {
            int src = g_src_sorted[e];
            const float4* xl4 = ((const float4*)g_xl) + (long)src * 64 + lane * 2;
            float4 l0 = xl4[0], l1 = xl4[1];
            float xlv[8] = {l0.x, l0.y, l0.z, l0.w, l1.x, l1.y, l1.z, l1.w};

            float p = 0.f;
#pragma unroll
            for (int j = 0; j < 8; j++) {
                float t = xlv[j] + xrv[j];
                t = (t > 0.f) ? t : NEG_SLOPE * t;
                p = fmaf(attv[j], t, p);
            }
            // reduce over the 8 lanes of this head
            p += __shfl_xor_sync(0xffffffffu, p, 4);
            p += __shfl_xor_sync(0xffffffffu, p, 2);
            p += __shfl_xor_sync(0xffffffffu, p, 1);

            if (p > m) {
                float sc = __expf(m - p);
                denom *= sc;
#pragma unroll
                for (int j = 0; j < 8; j++) acc[j] *= sc;
                m = p;
            }
            float w = __expf(p - m);
            denom += w;
#pragma unroll
            for (int j = 0; j < 8; j++) acc[j] = fmaf(w, xlv[j], acc[j]);
        }

        float inv = 1.f / (denom + 1e-16f);
        float v[8];
#pragma unroll
        for (int j = 0; j < 8; j++) v[j] = acc[j] * inv;
        // sum across the 4 heads (lanes l, l^8, l^16, l^24 share output channels)
#pragma unroll
        for (int j = 0; j < 8; j++) {
            v[j] += __shfl_xor_sync(0xffffffffu, v[j], 8);
            v[j] += __shfl_xor_sync(0xffffffffu, v[j], 16);
        }
        if (lane < 8) {
#pragma unroll
            for (int j = 0; j < 8; j++) {
                int c = lane * 8 + j;
                float o = 0.25f * v[j] + bias[c];
                g_out[(long)dst * C_OUT + c] = o;
                atomicAdd(&bsum[c], o);
                atomicAdd(&bsq[c], o * o);
            }
        }
    }
    __syncthreads();
    if (tid < C_OUT) {
        atomicAdd(&g_sum[tid], bsum[tid]);
        atomicAdd(&g_sumsq[tid], bsq[tid]);
    }
}

// ---------------- GraphNorm ----------------
__global__ void finalize_kernel(const float* __restrict__ gw,
                                const float* __restrict__ gms) {
    int c = threadIdx.x;
    const float invN = 1.f / (float)N_NODES;
    float mu  = g_sum[c] * invN;
    float msq = g_sumsq[c] * invN;
    float a   = gms[c];
    float var = msq - 2.f * a * mu * mu + a * a * mu * mu;
    g_scale[c] = gw[c] * rsqrtf(var + 1e-5f);
    g_shift[c] = a * mu;
}

__global__ void norm_kernel(const float* __restrict__ gb,
                            float* __restrict__ out) {
    int i = blockIdx.x * blockDim.x + threadIdx.x;
    const int total = N_NODES * C_OUT / 4;
    if (i >= total) return;
    float4 v = ((const float4*)g_out)[i];
    int c = (i & 15) * 4;
    v.x = g_scale[c + 0] * (v.x - g_shift[c + 0]) + gb[c + 0];
    v.y = g_scale[c + 1] * (v.y - g_shift[c + 1]) + gb[c + 1];
    v.z = g_scale[c + 2] * (v.z - g_shift[c + 2]) + gb[c + 2];
    v.w = g_scale[c + 3] * (v.w - g_shift[c + 3]) + gb[c + 3];
    ((float4*)out)[i] = v;
}

// ---------------- launch ----------------
extern "C" void kernel_launch(void* const* d_in, const int* in_sizes, int n_in,
                              void* d_out, int out_size) {
    const float* X    = (const float*)d_in[0];
    const int*   E    = (const int*)  d_in[1];
    const float* Wl   = (const float*)d_in[2];
    const float* Wr   = (const float*)d_in[3];
    const float* att  = (const float*)d_in[4];
    const float* bias = (const float*)d_in[5];
    const float* gw   = (const float*)d_in[6];
    const float* gb   = (const float*)d_in[7];
    const float* gms  = (const float*)d_in[8];
    float* out = (float*)d_out;

    zero_kernel<<<(N_NODES + 255) / 256, 256>>>();
    gemm_kernel<<<dim3(4, (N_NODES + 127) / 128), 256>>>(X, Wl, Wr);
    hist_kernel<<<(ET + 255) / 256, 256>>>(E);
    scan_kernel<<<1, 1024>>>();
    scatter_kernel<<<(ET + 255) / 256, 256>>>(E);
    attn_kernel<<<(N_NODES + 7) / 8, 256>>>(att, bias);
    finalize_kernel<<<1, C_OUT>>>(gw, gms);
    norm_kernel<<<(N_NODES * C_OUT / 4 + 255) / 256, 256>>>(gb, out);
}

// round 5
// speedup vs baseline: 1.6687x; 1.6687x over previous
#include <cuda_runtime.h>
#include <cuda_bf16.h>
#include <cstdint>
#include <math.h>

#define N_NODES 50000
#define N_PAD   50048          // padded to multiple of 128 for GEMM tiles
#define E_RAW   800000
#define ET      (E_RAW + N_NODES)
#define IN_F    256
#define HC      256            // HEADS * OUT_F
#define C_OUT   64
#define NEG_SLOPE 0.2f
#define NB_SCAN 49             // ceil(50000/1024)

// ---- scratch (static __device__ arrays; no runtime allocation) ----
__device__ float g_xl[N_NODES * HC];
__device__ float g_xr[N_NODES * HC];
__device__ float g_out[N_NODES * C_OUT];
__device__ int   g_counts[N_NODES];
__device__ int   g_cursor[N_NODES];
__device__ int   g_offsets[N_NODES + 1];
__device__ int   g_src_sorted[ET];
__device__ int   g_bsum[64];
__device__ int   g_boff[64];
__device__ float g_sum[C_OUT];
__device__ float g_sumsq[C_OUT];
__device__ float g_scale[C_OUT];
__device__ float g_shift[C_OUT];
// bf16 hi/lo splits
__device__ __align__(16) __nv_bfloat16 g_Xhi[N_PAD * IN_F];
__device__ __align__(16) __nv_bfloat16 g_Xlo[N_PAD * IN_F];
__device__ __align__(16) __nv_bfloat16 g_Bhi[512 * IN_F];   // [n][k]; n<256: Wl col, else Wr
__device__ __align__(16) __nv_bfloat16 g_Blo[512 * IN_F];

// ---------------- helpers ----------------
__device__ __forceinline__ uint32_t smem_u32(const void* p) {
    uint32_t a;
    asm("{ .reg .u64 t; cvta.to.shared.u64 t, %1; cvt.u32.u64 %0, t; }" : "=r"(a) : "l"(p));
    return a;
}
__device__ __forceinline__ void cp16(uint32_t s, const void* g) {
    asm volatile("cp.async.cg.shared.global [%0], [%1], 16;" :: "r"(s), "l"(g));
}
#define CP_COMMIT() asm volatile("cp.async.commit_group;" ::: "memory")
#define CP_WAIT1()  asm volatile("cp.async.wait_group 1;" ::: "memory")
#define CP_WAIT0()  asm volatile("cp.async.wait_group 0;" ::: "memory")

__device__ __forceinline__ void mma_bf16(float* d, const uint32_t* a, const uint32_t* b) {
    asm volatile(
        "mma.sync.aligned.m16n8k16.row.col.f32.bf16.bf16.f32 "
        "{%0,%1,%2,%3}, {%4,%5,%6,%7}, {%8,%9}, {%0,%1,%2,%3};"
        : "+f"(d[0]), "+f"(d[1]), "+f"(d[2]), "+f"(d[3])
        : "r"(a[0]), "r"(a[1]), "r"(a[2]), "r"(a[3]), "r"(b[0]), "r"(b[1]));
}

// ---------------- zero scratch ----------------
__global__ void zero_kernel() {
    int i = blockIdx.x * blockDim.x + threadIdx.x;
    if (i < N_NODES) { g_counts[i] = 0; g_cursor[i] = 0; }
    if (i < C_OUT)   { g_sum[i] = 0.f; g_sumsq[i] = 0.f; }
}

// ---------------- bf16 hi/lo conversion ----------------
__global__ void convx_kernel(const float* __restrict__ X) {
    int i = blockIdx.x * blockDim.x + threadIdx.x;
    const int total = N_NODES * IN_F / 4;
    if (i >= total) return;
    float4 v = ((const float4*)X)[i];
    __nv_bfloat16 h[4], l[4];
    float f[4] = {v.x, v.y, v.z, v.w};
#pragma unroll
    for (int j = 0; j < 4; j++) {
        h[j] = __float2bfloat16(f[j]);
        l[j] = __float2bfloat16(f[j] - __bfloat162float(h[j]));
    }
    ((uint2*)g_Xhi)[i] = *(uint2*)h;
    ((uint2*)g_Xlo)[i] = *(uint2*)l;
}

__global__ void padx_kernel() {  // zero the pad rows so pipeline reads are clean
    int i = blockIdx.x * blockDim.x + threadIdx.x;
    const int total = (N_PAD - N_NODES) * IN_F;
    if (i >= total) return;
    g_Xhi[N_NODES * IN_F + i] = __float2bfloat16(0.f);
    g_Xlo[N_NODES * IN_F + i] = __float2bfloat16(0.f);
}

__global__ void convb_kernel(const float* __restrict__ Wl, const float* __restrict__ Wr) {
    int i = blockIdx.x * blockDim.x + threadIdx.x;   // over 512*256
    if (i >= 512 * IN_F) return;
    int n = i >> 8, k = i & 255;
    const float* W = (n < 256) ? Wl : Wr;
    float v = W[k * 256 + (n & 255)];
    __nv_bfloat16 h = __float2bfloat16(v);
    __nv_bfloat16 l = __float2bfloat16(v - __bfloat162float(h));
    g_Bhi[n * IN_F + k] = h;
    g_Blo[n * IN_F + k] = l;
}

// ---------------- mma.sync GEMM: Y[50000,512] = X @ [Wl|Wr] ----------------
// grid(4, 391): bx = 128-col tile of the 512 output cols; by = 128-row tile.
// bf16 hi/lo 3-product split, fp32 accum. cp.async depth-2 pipeline.
#define LDB   40               // padded k-stride (elems) -> conflict-free LDS
#define TSZ   (128 * LDB)      // one operand tile, elems (5120)
#define BUFSZ (4 * TSZ)        // A_hi|A_lo|B_hi|B_lo (20480 elems = 40960 B)
#define GSMEM (2 * BUFSZ * 2)  // bytes: 81920

__global__ void __launch_bounds__(256) gemm_mma_kernel() {
    extern __shared__ __align__(16) char dsm[];
    __nv_bfloat16* sm = (__nv_bfloat16*)dsm;
    uint32_t sb = smem_u32(dsm);

    const int tid = threadIdx.x;
    const int wid = tid >> 5, lane = tid & 31;
    const int wm = wid & 3, wn = wid >> 2;          // 4 warps on M, 2 on N
    const int q = lane >> 2, c2 = (lane & 3) * 2;
    const int bx = blockIdx.x, by = blockIdx.y;
    const int rowG = by * 128;

    float acc[2][8][4];
#pragma unroll
    for (int mt = 0; mt < 2; mt++)
#pragma unroll
        for (int nt = 0; nt < 8; nt++)
#pragma unroll
            for (int j = 0; j < 4; j++) acc[mt][nt][j] = 0.f;

    // prefetch lambda: chunk c -> buffer b
    auto prefetch = [&](int c, int b) {
        const int k0 = c * 32;
        const uint32_t base = sb + b * (BUFSZ * 2);
#pragma unroll
        for (int i = 0; i < 2; i++) {               // A: 512 16B-vectors
            int idx = tid + i * 256;
            int r = idx >> 2, seg = idx & 3;
            uint32_t so = base + (r * LDB + seg * 8) * 2;
            long g = (long)(rowG + r) * IN_F + k0 + seg * 8;
            cp16(so,            g_Xhi + g);
            cp16(so + TSZ * 2,  g_Xlo + g);
        }
#pragma unroll
        for (int i = 0; i < 2; i++) {               // B
            int idx = tid + i * 256;
            int r = idx >> 2, seg = idx & 3;
            uint32_t so = base + (2 * TSZ + r * LDB + seg * 8) * 2;
            long g = (long)(bx * 128 + r) * IN_F + k0 + seg * 8;
            cp16(so,            g_Bhi + g);
            cp16(so + TSZ * 2,  g_Blo + g);
        }
        CP_COMMIT();
    };

    prefetch(0, 0);
    for (int c = 0; c < 8; c++) {
        if (c < 7) prefetch(c + 1, (c + 1) & 1);
        if (c < 7) { CP_WAIT1(); } else { CP_WAIT0(); }
        __syncthreads();

        const __nv_bfloat16* Ah = sm + (c & 1) * BUFSZ;
        const __nv_bfloat16* Al = Ah + TSZ;
        const __nv_bfloat16* Bh = Ah + 2 * TSZ;
        const __nv_bfloat16* Bl = Ah + 3 * TSZ;

#pragma unroll
        for (int ks = 0; ks < 2; ks++) {
            const int kk = ks * 16;
            uint32_t ah[2][4], al[2][4];
#pragma unroll
            for (int mt = 0; mt < 2; mt++) {
                int rb = wm * 32 + mt * 16;
                ah[mt][0] = *(const uint32_t*)(Ah + (rb + q) * LDB + kk + c2);
                ah[mt][1] = *(const uint32_t*)(Ah + (rb + q + 8) * LDB + kk + c2);
                ah[mt][2] = *(const uint32_t*)(Ah + (rb + q) * LDB + kk + c2 + 8);
                ah[mt][3] = *(const uint32_t*)(Ah + (rb + q + 8) * LDB + kk + c2 + 8);
                al[mt][0] = *(const uint32_t*)(Al + (rb + q) * LDB + kk + c2);
                al[mt][1] = *(const uint32_t*)(Al + (rb + q + 8) * LDB + kk + c2);
                al[mt][2] = *(const uint32_t*)(Al + (rb + q) * LDB + kk + c2 + 8);
                al[mt][3] = *(const uint32_t*)(Al + (rb + q + 8) * LDB + kk + c2 + 8);
            }
            uint32_t bh[8][2], bl[8][2];
#pragma unroll
            for (int nt = 0; nt < 8; nt++) {
                int nb = wn * 64 + nt * 8;
                bh[nt][0] = *(const uint32_t*)(Bh + (nb + q) * LDB + kk + c2);
                bh[nt][1] = *(const uint32_t*)(Bh + (nb + q) * LDB + kk + c2 + 8);
                bl[nt][0] = *(const uint32_t*)(Bl + (nb + q) * LDB + kk + c2);
                bl[nt][1] = *(const uint32_t*)(Bl + (nb + q) * LDB + kk + c2 + 8);
            }
#pragma unroll
            for (int mt = 0; mt < 2; mt++)
#pragma unroll
                for (int nt = 0; nt < 8; nt++) {
                    mma_bf16(acc[mt][nt], ah[mt], bh[nt]);
                    mma_bf16(acc[mt][nt], ah[mt], bl[nt]);
                    mma_bf16(acc[mt][nt], al[mt], bh[nt]);
                }
        }
        __syncthreads();
    }

    // epilogue
    float* Y = (bx < 2) ? g_xl : g_xr;
    const int colBase = (bx & 1) * 128;
#pragma unroll
    for (int mt = 0; mt < 2; mt++) {
        int r0 = rowG + wm * 32 + mt * 16 + q;
#pragma unroll
        for (int nt = 0; nt < 8; nt++) {
            int col = colBase + wn * 64 + nt * 8 + c2;
            if (r0 < N_NODES)
                *(float2*)(Y + (long)r0 * HC + col) = make_float2(acc[mt][nt][0], acc[mt][nt][1]);
            if (r0 + 8 < N_NODES)
                *(float2*)(Y + (long)(r0 + 8) * HC + col) = make_float2(acc[mt][nt][2], acc[mt][nt][3]);
        }
    }
}

// ---------------- CSR build (dst-sorted) ----------------
__global__ void hist_kernel(const int* __restrict__ E) {
    int i = blockIdx.x * blockDim.x + threadIdx.x;
    if (i >= ET) return;
    int d = (i < E_RAW) ? E[E_RAW + i] : (i - E_RAW);
    atomicAdd(&g_counts[d], 1);
}

__global__ void scan1_kernel() {   // 49 blocks x 1024: local inclusive scan + block sums
    __shared__ int sh[1024];
    int b = blockIdx.x, t = threadIdx.x;
    int i = b * 1024 + t;
    int v = (i < N_NODES) ? g_counts[i] : 0;
    sh[t] = v;
    __syncthreads();
    for (int off = 1; off < 1024; off <<= 1) {
        int add = (t >= off) ? sh[t - off] : 0;
        __syncthreads();
        sh[t] += add;
        __syncthreads();
    }
    if (i < N_NODES) g_offsets[i + 1] = sh[t];
    if (t == 1023) g_bsum[b] = sh[1023];
}

__global__ void scan2_kernel() {   // 1 block x 64: exclusive scan of block sums
    __shared__ int sh[64];
    int t = threadIdx.x;
    int v = (t < NB_SCAN) ? g_bsum[t] : 0;
    sh[t] = v;
    __syncthreads();
    for (int off = 1; off < 64; off <<= 1) {
        int add = (t >= off) ? sh[t - off] : 0;
        __syncthreads();
        sh[t] += add;
        __syncthreads();
    }
    if (t < NB_SCAN) g_boff[t] = sh[t] - v;
}

__global__ void scan3_kernel() {
    int b = blockIdx.x;
    int i = b * 1024 + threadIdx.x;
    if (i < N_NODES) g_offsets[i + 1] += g_boff[b];
    if (i == 0) g_offsets[0] = 0;
}

__global__ void scatter_kernel(const int* __restrict__ E) {
    int i = blockIdx.x * blockDim.x + threadIdx.x;
    if (i >= ET) return;
    int s, d;
    if (i < E_RAW) { s = E[i]; d = E[E_RAW + i]; }
    else           { s = d = i - E_RAW; }
    int pos = atomicAdd(&g_cursor[d], 1);
    g_src_sorted[g_offsets[d] + pos] = s;
}

// ---------------- attention: one warp per destination node ----------------
__global__ void attn_kernel(const float* __restrict__ att,
                            const float* __restrict__ bias) {
    __shared__ float bsum[C_OUT];
    __shared__ float bsq[C_OUT];
    int tid = threadIdx.x;
    if (tid < C_OUT) { bsum[tid] = 0.f; bsq[tid] = 0.f; }
    __syncthreads();

    int warp = (blockIdx.x * blockDim.x + tid) >> 5;
    int lane = tid & 31;

    if (warp < N_NODES) {
        int dst = warp;
        const float4* xr4 = ((const float4*)g_xr) + (long)dst * 64 + lane * 2;
        float4 r0 = xr4[0], r1 = xr4[1];
        float xrv[8] = {r0.x, r0.y, r0.z, r0.w, r1.x, r1.y, r1.z, r1.w};
        float4 a0 = ((const float4*)att)[lane * 2];
        float4 a1 = ((const float4*)att)[lane * 2 + 1];
        float attv[8] = {a0.x, a0.y, a0.z, a0.w, a1.x, a1.y, a1.z, a1.w};

        float m = -1e30f, denom = 0.f;
        float acc[8] = {0.f, 0.f, 0.f, 0.f, 0.f, 0.f, 0.f, 0.f};

        int e0 = g_offsets[dst], e1 = g_offsets[dst + 1];
        for (int e = e0; e < e1; e++) {
            int src = g_src_sorted[e];
            const float4* xl4 = ((const float4*)g_xl) + (long)src * 64 + lane * 2;
            float4 l0 = xl4[0], l1 = xl4[1];
            float xlv[8] = {l0.x, l0.y, l0.z, l0.w, l1.x, l1.y, l1.z, l1.w};

            float p = 0.f;
#pragma unroll
            for (int j = 0; j < 8; j++) {
                float t = xlv[j] + xrv[j];
                t = (t > 0.f) ? t : NEG_SLOPE * t;
                p = fmaf(attv[j], t, p);
            }
            p += __shfl_xor_sync(0xffffffffu, p, 4);
            p += __shfl_xor_sync(0xffffffffu, p, 2);
            p += __shfl_xor_sync(0xffffffffu, p, 1);

            if (p > m) {
                float sc = __expf(m - p);
                denom *= sc;
#pragma unroll
                for (int j = 0; j < 8; j++) acc[j] *= sc;
                m = p;
            }
            float w = __expf(p - m);
            denom += w;
#pragma unroll
            for (int j = 0; j < 8; j++) acc[j] = fmaf(w, xlv[j], acc[j]);
        }

        float inv = 1.f / (denom + 1e-16f);
        float v[8];
#pragma unroll
        for (int j = 0; j < 8; j++) v[j] = acc[j] * inv;
#pragma unroll
        for (int j = 0; j < 8; j++) {
            v[j] += __shfl_xor_sync(0xffffffffu, v[j], 8);
            v[j] += __shfl_xor_sync(0xffffffffu, v[j], 16);
        }
        if (lane < 8) {
#pragma unroll
            for (int j = 0; j < 8; j++) {
                int c = lane * 8 + j;
                float o = 0.25f * v[j] + bias[c];
                g_out[(long)dst * C_OUT + c] = o;
                atomicAdd(&bsum[c], o);
                atomicAdd(&bsq[c], o * o);
            }
        }
    }
    __syncthreads();
    if (tid < C_OUT) {
        atomicAdd(&g_sum[tid], bsum[tid]);
        atomicAdd(&g_sumsq[tid], bsq[tid]);
    }
}

// ---------------- GraphNorm ----------------
__global__ void finalize_kernel(const float* __restrict__ gw,
                                const float* __restrict__ gms) {
    int c = threadIdx.x;
    const float invN = 1.f / (float)N_NODES;
    float mu  = g_sum[c] * invN;
    float msq = g_sumsq[c] * invN;
    float a   = gms[c];
    float var = msq - 2.f * a * mu * mu + a * a * mu * mu;
    g_scale[c] = gw[c] * rsqrtf(var + 1e-5f);
    g_shift[c] = a * mu;
}

__global__ void norm_kernel(const float* __restrict__ gb,
                            float* __restrict__ out) {
    int i = blockIdx.x * blockDim.x + threadIdx.x;
    const int total = N_NODES * C_OUT / 4;
    if (i >= total) return;
    float4 v = ((const float4*)g_out)[i];
    int c = (i & 15) * 4;
    v.x = g_scale[c + 0] * (v.x - g_shift[c + 0]) + gb[c + 0];
    v.y = g_scale[c + 1] * (v.y - g_shift[c + 1]) + gb[c + 1];
    v.z = g_scale[c + 2] * (v.z - g_shift[c + 2]) + gb[c + 2];
    v.w = g_scale[c + 3] * (v.w - g_shift[c + 3]) + gb[c + 3];
    ((float4*)out)[i] = v;
}

// ---------------- launch ----------------
extern "C" void kernel_launch(void* const* d_in, const int* in_sizes, int n_in,
                              void* d_out, int out_size) {
    const float* X    = (const float*)d_in[0];
    const int*   E    = (const int*)  d_in[1];
    const float* Wl   = (const float*)d_in[2];
    const float* Wr   = (const float*)d_in[3];
    const float* att  = (const float*)d_in[4];
    const float* bias = (const float*)d_in[5];
    const float* gw   = (const float*)d_in[6];
    const float* gb   = (const float*)d_in[7];
    const float* gms  = (const float*)d_in[8];
    float* out = (float*)d_out;

    cudaFuncSetAttribute(gemm_mma_kernel, cudaFuncAttributeMaxDynamicSharedMemorySize, GSMEM);

    zero_kernel<<<(N_NODES + 255) / 256, 256>>>();
    convx_kernel<<<(N_NODES * IN_F / 4 + 255) / 256, 256>>>(X);
    padx_kernel<<<((N_PAD - N_NODES) * IN_F + 255) / 256, 256>>>();
    convb_kernel<<<(512 * IN_F + 255) / 256, 256>>>(Wl, Wr);
    gemm_mma_kernel<<<dim3(4, N_PAD / 128), 256, GSMEM>>>();
    hist_kernel<<<(ET + 255) / 256, 256>>>(E);
    scan1_kernel<<<NB_SCAN, 1024>>>();
    scan2_kernel<<<1, 64>>>();
    scan3_kernel<<<NB_SCAN, 1024>>>();
    scatter_kernel<<<(ET + 255) / 256, 256>>>(E);
    attn_kernel<<<(N_NODES + 7) / 8, 256>>>(att, bias);
    finalize_kernel<<<1, C_OUT>>>(gw, gms);
    norm_kernel<<<(N_NODES * C_OUT / 4 + 255) / 256, 256>>>(gb, out);
}

// round 6
// speedup vs baseline: 1.9757x; 1.1840x over previous
#include <cuda_runtime.h>
#include <cuda_fp16.h>
#include <cstdint>
#include <math.h>

#define N_NODES 50000
#define N_PAD   50048          // padded to multiple of 128 for GEMM tiles
#define E_RAW   800000
#define ET      (E_RAW + N_NODES)
#define IN_F    256
#define HC      256            // HEADS * OUT_F
#define C_OUT   64
#define NEG_SLOPE 0.2f
#define NB_SCAN 49             // ceil(50000/1024)

// ---- scratch (static __device__ arrays; no runtime allocation) ----
__device__ float g_xl[N_NODES * HC];
__device__ float g_xr[N_NODES * HC];
__device__ float g_out[N_NODES * C_OUT];
__device__ int   g_counts[N_NODES];
__device__ int   g_cursor[N_NODES];
__device__ int   g_offsets[N_NODES + 1];
__device__ int   g_src_sorted[ET];
__device__ int   g_bsum[64];
__device__ int   g_boff[64];
__device__ float g_sum[C_OUT];
__device__ float g_sumsq[C_OUT];
__device__ float g_scale[C_OUT];
__device__ float g_shift[C_OUT];
// fp16 operands: X rounded to fp16; W split hi/lo fp16 (2-term correction)
__device__ __align__(16) __half g_Xh[N_PAD * IN_F];
__device__ __align__(16) __half g_Bh[512 * IN_F];   // [n][k]; n<256: Wl col, else Wr
__device__ __align__(16) __half g_Bl[512 * IN_F];

// ---------------- helpers ----------------
__device__ __forceinline__ uint32_t smem_u32(const void* p) {
    uint32_t a;
    asm("{ .reg .u64 t; cvta.to.shared.u64 t, %1; cvt.u32.u64 %0, t; }" : "=r"(a) : "l"(p));
    return a;
}
__device__ __forceinline__ void cp16(uint32_t s, const void* g) {
    asm volatile("cp.async.cg.shared.global [%0], [%1], 16;" :: "r"(s), "l"(g));
}
#define CP_COMMIT() asm volatile("cp.async.commit_group;" ::: "memory")
#define CP_WAIT1()  asm volatile("cp.async.wait_group 1;" ::: "memory")
#define CP_WAIT0()  asm volatile("cp.async.wait_group 0;" ::: "memory")

__device__ __forceinline__ void mma_fp16(float* d, const uint32_t* a, const uint32_t* b) {
    asm volatile(
        "mma.sync.aligned.m16n8k16.row.col.f32.f16.f16.f32 "
        "{%0,%1,%2,%3}, {%4,%5,%6,%7}, {%8,%9}, {%0,%1,%2,%3};"
        : "+f"(d[0]), "+f"(d[1]), "+f"(d[2]), "+f"(d[3])
        : "r"(a[0]), "r"(a[1]), "r"(a[2]), "r"(a[3]), "r"(b[0]), "r"(b[1]));
}

// ---------------- zero scratch ----------------
__global__ void zero_kernel() {
    int i = blockIdx.x * blockDim.x + threadIdx.x;
    if (i < N_NODES) { g_counts[i] = 0; g_cursor[i] = 0; }
    if (i < C_OUT)   { g_sum[i] = 0.f; g_sumsq[i] = 0.f; }
}

// ---------------- fp16 conversion ----------------
__global__ void convx_kernel(const float* __restrict__ X) {
    int i = blockIdx.x * blockDim.x + threadIdx.x;
    const int total = N_NODES * IN_F / 4;
    if (i >= total) return;
    float4 v = ((const float4*)X)[i];
    __half h[4] = {__float2half_rn(v.x), __float2half_rn(v.y),
                   __float2half_rn(v.z), __float2half_rn(v.w)};
    ((uint2*)g_Xh)[i] = *(uint2*)h;
}

__global__ void padx_kernel() {
    int i = blockIdx.x * blockDim.x + threadIdx.x;
    const int total = (N_PAD - N_NODES) * IN_F;
    if (i >= total) return;
    g_Xh[N_NODES * IN_F + i] = __float2half_rn(0.f);
}

__global__ void convb_kernel(const float* __restrict__ Wl, const float* __restrict__ Wr) {
    int i = blockIdx.x * blockDim.x + threadIdx.x;   // over 512*256
    if (i >= 512 * IN_F) return;
    int n = i >> 8, k = i & 255;
    const float* W = (n < 256) ? Wl : Wr;
    float v = W[k * 256 + (n & 255)];
    __half h = __float2half_rn(v);
    __half l = __float2half_rn(v - __half2float(h));
    g_Bh[n * IN_F + k] = h;
    g_Bl[n * IN_F + k] = l;
}

// ---------------- mma.sync GEMM: Y[50000,512] = X @ [Wl|Wr] ----------------
// grid(4, 391). fp16 2-term split (Xh*Wh + Xh*Wl), fp32 accum, cp.async depth-2.
#define LDB   40               // padded k-stride (halfs) -> conflict-free LDS
#define TSZ   (128 * LDB)      // one operand tile, elems (5120)
#define BUFSZ (3 * TSZ)        // Ah | Bh | Bl
#define GSMEM (2 * BUFSZ * 2)  // bytes: 61440

__global__ void __launch_bounds__(256) gemm_mma_kernel() {
    extern __shared__ __align__(16) char dsm[];
    __half* sm = (__half*)dsm;
    uint32_t sb = smem_u32(dsm);

    const int tid = threadIdx.x;
    const int wid = tid >> 5, lane = tid & 31;
    const int wm = wid & 3, wn = wid >> 2;          // 4 warps on M, 2 on N
    const int q = lane >> 2, c2 = (lane & 3) * 2;
    const int bx = blockIdx.x, by = blockIdx.y;
    const int rowG = by * 128;

    float acc[2][8][4];
#pragma unroll
    for (int mt = 0; mt < 2; mt++)
#pragma unroll
        for (int nt = 0; nt < 8; nt++)
#pragma unroll
            for (int j = 0; j < 4; j++) acc[mt][nt][j] = 0.f;

    auto prefetch = [&](int c, int b) {
        const int k0 = c * 32;
        const uint32_t base = sb + b * (BUFSZ * 2);
#pragma unroll
        for (int i = 0; i < 2; i++) {
            int idx = tid + i * 256;
            int r = idx >> 2, seg = idx & 3;
            uint32_t off = (r * LDB + seg * 8) * 2;
            long ga = (long)(rowG + r) * IN_F + k0 + seg * 8;
            long gb = (long)(bx * 128 + r) * IN_F + k0 + seg * 8;
            cp16(base + off,               g_Xh + ga);
            cp16(base + TSZ * 2 + off,     g_Bh + gb);
            cp16(base + 2 * TSZ * 2 + off, g_Bl + gb);
        }
        CP_COMMIT();
    };

    prefetch(0, 0);
    for (int c = 0; c < 8; c++) {
        if (c < 7) { prefetch(c + 1, (c + 1) & 1); CP_WAIT1(); }
        else       { CP_WAIT0(); }
        __syncthreads();

        const __half* Ah = sm + (c & 1) * BUFSZ;
        const __half* Bh = Ah + TSZ;
        const __half* Bl = Ah + 2 * TSZ;

#pragma unroll
        for (int ks = 0; ks < 2; ks++) {
            const int kk = ks * 16;
            uint32_t ah[2][4];
#pragma unroll
            for (int mt = 0; mt < 2; mt++) {
                int rb = wm * 32 + mt * 16;
                ah[mt][0] = *(const uint32_t*)(Ah + (rb + q) * LDB + kk + c2);
                ah[mt][1] = *(const uint32_t*)(Ah + (rb + q + 8) * LDB + kk + c2);
                ah[mt][2] = *(const uint32_t*)(Ah + (rb + q) * LDB + kk + c2 + 8);
                ah[mt][3] = *(const uint32_t*)(Ah + (rb + q + 8) * LDB + kk + c2 + 8);
            }
            uint32_t bh[8][2], bl[8][2];
#pragma unroll
            for (int nt = 0; nt < 8; nt++) {
                int nb = wn * 64 + nt * 8;
                bh[nt][0] = *(const uint32_t*)(Bh + (nb + q) * LDB + kk + c2);
                bh[nt][1] = *(const uint32_t*)(Bh + (nb + q) * LDB + kk + c2 + 8);
                bl[nt][0] = *(const uint32_t*)(Bl + (nb + q) * LDB + kk + c2);
                bl[nt][1] = *(const uint32_t*)(Bl + (nb + q) * LDB + kk + c2 + 8);
            }
#pragma unroll
            for (int mt = 0; mt < 2; mt++)
#pragma unroll
                for (int nt = 0; nt < 8; nt++) {
                    mma_fp16(acc[mt][nt], ah[mt], bh[nt]);
                    mma_fp16(acc[mt][nt], ah[mt], bl[nt]);
                }
        }
        __syncthreads();
    }

    float* Y = (bx < 2) ? g_xl : g_xr;
    const int colBase = (bx & 1) * 128;
#pragma unroll
    for (int mt = 0; mt < 2; mt++) {
        int r0 = rowG + wm * 32 + mt * 16 + q;
#pragma unroll
        for (int nt = 0; nt < 8; nt++) {
            int col = colBase + wn * 64 + nt * 8 + c2;
            if (r0 < N_NODES)
                *(float2*)(Y + (long)r0 * HC + col) = make_float2(acc[mt][nt][0], acc[mt][nt][1]);
            if (r0 + 8 < N_NODES)
                *(float2*)(Y + (long)(r0 + 8) * HC + col) = make_float2(acc[mt][nt][2], acc[mt][nt][3]);
        }
    }
}

// ---------------- CSR build (dst-sorted) ----------------
__global__ void hist_kernel(const int* __restrict__ E) {
    int i = blockIdx.x * blockDim.x + threadIdx.x;
    if (i >= ET) return;
    int d = (i < E_RAW) ? E[E_RAW + i] : (i - E_RAW);
    atomicAdd(&g_counts[d], 1);
}

__global__ void scan1_kernel() {
    __shared__ int sh[1024];
    int b = blockIdx.x, t = threadIdx.x;
    int i = b * 1024 + t;
    int v = (i < N_NODES) ? g_counts[i] : 0;
    sh[t] = v;
    __syncthreads();
    for (int off = 1; off < 1024; off <<= 1) {
        int add = (t >= off) ? sh[t - off] : 0;
        __syncthreads();
        sh[t] += add;
        __syncthreads();
    }
    if (i < N_NODES) g_offsets[i + 1] = sh[t];
    if (t == 1023) g_bsum[b] = sh[1023];
}

__global__ void scan2_kernel() {
    __shared__ int sh[64];
    int t = threadIdx.x;
    int v = (t < NB_SCAN) ? g_bsum[t] : 0;
    sh[t] = v;
    __syncthreads();
    for (int off = 1; off < 64; off <<= 1) {
        int add = (t >= off) ? sh[t - off] : 0;
        __syncthreads();
        sh[t] += add;
        __syncthreads();
    }
    if (t < NB_SCAN) g_boff[t] = sh[t] - v;
}

__global__ void scan3_kernel() {
    int b = blockIdx.x;
    int i = b * 1024 + threadIdx.x;
    if (i < N_NODES) g_offsets[i + 1] += g_boff[b];
    if (i == 0) g_offsets[0] = 0;
}

__global__ void scatter_kernel(const int* __restrict__ E) {
    int i = blockIdx.x * blockDim.x + threadIdx.x;
    if (i >= ET) return;
    int s, d;
    if (i < E_RAW) { s = E[i]; d = E[E_RAW + i]; }
    else           { s = d = i - E_RAW; }
    int pos = atomicAdd(&g_cursor[d], 1);
    g_src_sorted[g_offsets[d] + pos] = s;
}

// ---------------- attention: one warp per destination node ----------------
// 4-edge software pipeline, branchless online softmax.
__global__ void attn_kernel(const float* __restrict__ att,
                            const float* __restrict__ bias) {
    __shared__ float bsum[C_OUT];
    __shared__ float bsq[C_OUT];
    int tid = threadIdx.x;
    if (tid < C_OUT) { bsum[tid] = 0.f; bsq[tid] = 0.f; }
    __syncthreads();

    int warp = (blockIdx.x * blockDim.x + tid) >> 5;
    int lane = tid & 31;

    if (warp < N_NODES) {
        int dst = warp;
        const float4* xr4 = ((const float4*)g_xr) + (long)dst * 64 + lane * 2;
        float4 r0 = xr4[0], r1 = xr4[1];
        float xrv[8] = {r0.x, r0.y, r0.z, r0.w, r1.x, r1.y, r1.z, r1.w};
        float4 a0 = ((const float4*)att)[lane * 2];
        float4 a1 = ((const float4*)att)[lane * 2 + 1];
        float attv[8] = {a0.x, a0.y, a0.z, a0.w, a1.x, a1.y, a1.z, a1.w};

        float m = -1e30f, denom = 0.f;
        float acc[8] = {0.f, 0.f, 0.f, 0.f, 0.f, 0.f, 0.f, 0.f};

        const int e0 = g_offsets[dst], e1 = g_offsets[dst + 1];
        int e = e0;
        const int nq = (e1 - e0) >> 2;

        for (int itq = 0; itq < nq; itq++, e += 4) {
            float4 L0[4], L1[4];
#pragma unroll
            for (int u = 0; u < 4; u++) {
                int s = g_src_sorted[e + u];
                const float4* p4 = ((const float4*)g_xl) + (long)s * 64 + lane * 2;
                L0[u] = p4[0]; L1[u] = p4[1];
            }
            float p[4];
#pragma unroll
            for (int u = 0; u < 4; u++) {
                float xlv[8] = {L0[u].x, L0[u].y, L0[u].z, L0[u].w,
                                L1[u].x, L1[u].y, L1[u].z, L1[u].w};
                float pp = 0.f;
#pragma unroll
                for (int j = 0; j < 8; j++) {
                    float t = xlv[j] + xrv[j];
                    t = (t > 0.f) ? t : NEG_SLOPE * t;
                    pp = fmaf(attv[j], t, pp);
                }
                p[u] = pp;
            }
            // interleaved shfl reductions (ILP across the 4 chains)
#pragma unroll
            for (int u = 0; u < 4; u++) p[u] += __shfl_xor_sync(0xffffffffu, p[u], 4);
#pragma unroll
            for (int u = 0; u < 4; u++) p[u] += __shfl_xor_sync(0xffffffffu, p[u], 2);
#pragma unroll
            for (int u = 0; u < 4; u++) p[u] += __shfl_xor_sync(0xffffffffu, p[u], 1);
            // sequential branchless updates
#pragma unroll
            for (int u = 0; u < 4; u++) {
                float mn = fmaxf(m, p[u]);
                float sc = __expf(m - mn);
                float w  = __expf(p[u] - mn);
                m = mn;
                denom = fmaf(denom, sc, w);
                float xlv[8] = {L0[u].x, L0[u].y, L0[u].z, L0[u].w,
                                L1[u].x, L1[u].y, L1[u].z, L1[u].w};
#pragma unroll
                for (int j = 0; j < 8; j++) acc[j] = fmaf(acc[j], sc, w * xlv[j]);
            }
        }
        for (; e < e1; e++) {
            int s = g_src_sorted[e];
            const float4* p4 = ((const float4*)g_xl) + (long)s * 64 + lane * 2;
            float4 l0 = p4[0], l1 = p4[1];
            float xlv[8] = {l0.x, l0.y, l0.z, l0.w, l1.x, l1.y, l1.z, l1.w};
            float pp = 0.f;
#pragma unroll
            for (int j = 0; j < 8; j++) {
                float t = xlv[j] + xrv[j];
                t = (t > 0.f) ? t : NEG_SLOPE * t;
                pp = fmaf(attv[j], t, pp);
            }
            pp += __shfl_xor_sync(0xffffffffu, pp, 4);
            pp += __shfl_xor_sync(0xffffffffu, pp, 2);
            pp += __shfl_xor_sync(0xffffffffu, pp, 1);
            float mn = fmaxf(m, pp);
            float sc = __expf(m - mn);
            float w  = __expf(pp - mn);
            m = mn;
            denom = fmaf(denom, sc, w);
#pragma unroll
            for (int j = 0; j < 8; j++) acc[j] = fmaf(acc[j], sc, w * xlv[j]);
        }

        float inv = 1.f / (denom + 1e-16f);
        float v[8];
#pragma unroll
        for (int j = 0; j < 8; j++) v[j] = acc[j] * inv;
#pragma unroll
        for (int j = 0; j < 8; j++) {
            v[j] += __shfl_xor_sync(0xffffffffu, v[j], 8);
            v[j] += __shfl_xor_sync(0xffffffffu, v[j], 16);
        }
        if (lane < 8) {
#pragma unroll
            for (int j = 0; j < 8; j++) {
                int c = lane * 8 + j;
                float o = 0.25f * v[j] + bias[c];
                g_out[(long)dst * C_OUT + c] = o;
                atomicAdd(&bsum[c], o);
                atomicAdd(&bsq[c], o * o);
            }
        }
    }
    __syncthreads();
    if (tid < C_OUT) {
        atomicAdd(&g_sum[tid], bsum[tid]);
        atomicAdd(&g_sumsq[tid], bsq[tid]);
    }
}

// ---------------- GraphNorm ----------------
__global__ void finalize_kernel(const float* __restrict__ gw,
                                const float* __restrict__ gms) {
    int c = threadIdx.x;
    const float invN = 1.f / (float)N_NODES;
    float mu  = g_sum[c] * invN;
    float msq = g_sumsq[c] * invN;
    float a   = gms[c];
    float var = msq - 2.f * a * mu * mu + a * a * mu * mu;
    g_scale[c] = gw[c] * rsqrtf(var + 1e-5f);
    g_shift[c] = a * mu;
}

__global__ void norm_kernel(const float* __restrict__ gb,
                            float* __restrict__ out) {
    int i = blockIdx.x * blockDim.x + threadIdx.x;
    const int total = N_NODES * C_OUT / 4;
    if (i >= total) return;
    float4 v = ((const float4*)g_out)[i];
    int c = (i & 15) * 4;
    v.x = g_scale[c + 0] * (v.x - g_shift[c + 0]) + gb[c + 0];
    v.y = g_scale[c + 1] * (v.y - g_shift[c + 1]) + gb[c + 1];
    v.z = g_scale[c + 2] * (v.z - g_shift[c + 2]) + gb[c + 2];
    v.w = g_scale[c + 3] * (v.w - g_shift[c + 3]) + gb[c + 3];
    ((float4*)out)[i] = v;
}

// ---------------- launch ----------------
extern "C" void kernel_launch(void* const* d_in, const int* in_sizes, int n_in,
                              void* d_out, int out_size) {
    const float* X    = (const float*)d_in[0];
    const int*   E    = (const int*)  d_in[1];
    const float* Wl   = (const float*)d_in[2];
    const float* Wr   = (const float*)d_in[3];
    const float* att  = (const float*)d_in[4];
    const float* bias = (const float*)d_in[5];
    const float* gw   = (const float*)d_in[6];
    const float* gb   = (const float*)d_in[7];
    const float* gms  = (const float*)d_in[8];
    float* out = (float*)d_out;

    cudaFuncSetAttribute(gemm_mma_kernel, cudaFuncAttributeMaxDynamicSharedMemorySize, GSMEM);

    zero_kernel<<<(N_NODES + 255) / 256, 256>>>();
    convx_kernel<<<(N_NODES * IN_F / 4 + 255) / 256, 256>>>(X);
    padx_kernel<<<((N_PAD - N_NODES) * IN_F + 255) / 256, 256>>>();
    convb_kernel<<<(512 * IN_F + 255) / 256, 256>>>(Wl, Wr);
    gemm_mma_kernel<<<dim3(4, N_PAD / 128), 256, GSMEM>>>();
    hist_kernel<<<(ET + 255) / 256, 256>>>(E);
    scan1_kernel<<<NB_SCAN, 1024>>>();
    scan2_kernel<<<1, 64>>>();
    scan3_kernel<<<NB_SCAN, 1024>>>();
    scatter_kernel<<<(ET + 255) / 256, 256>>>(E);
    attn_kernel<<<(N_NODES + 7) / 8, 256>>>(att, bias);
    finalize_kernel<<<1, C_OUT>>>(gw, gms);
    norm_kernel<<<(N_NODES * C_OUT / 4 + 255) / 256, 256>>>(gb, out);
}

// round 7
// speedup vs baseline: 2.0645x; 1.0449x over previous
#include <cuda_runtime.h>
#include <cuda_fp16.h>
#include <cstdint>
#include <math.h>

#define N_NODES 50000
#define N_PAD   50048          // padded to multiple of 128 for GEMM tiles
#define E_RAW   800000
#define ET      (E_RAW + N_NODES)
#define IN_F    256
#define HC      256            // HEADS * OUT_F
#define C_OUT   64
#define NEG_SLOPE 0.2f
#define NB_SCAN 49             // ceil(50000/1024)

// ---- scratch (static __device__ arrays; no runtime allocation) ----
__device__ __align__(16) __half g_xlh[N_NODES * HC];   // xl in fp16 (attn gathers this)
__device__ float g_xr[N_NODES * HC];
__device__ float g_out[N_NODES * C_OUT];
__device__ int   g_counts[N_NODES];
__device__ int   g_cursor[N_NODES];
__device__ int   g_offsets[N_NODES + 1];
__device__ int   g_src_sorted[ET];
__device__ int   g_bsum[64];
__device__ int   g_boff[64];
__device__ float g_sum[C_OUT];
__device__ float g_sumsq[C_OUT];
__device__ float g_scale[C_OUT];
__device__ float g_shift[C_OUT];
// fp16 operands: X rounded to fp16; W split hi/lo fp16 (2-term correction)
__device__ __align__(16) __half g_Xh[N_PAD * IN_F];
__device__ __align__(16) __half g_Bh[512 * IN_F];   // [n][k]; n<256: Wl col, else Wr
__device__ __align__(16) __half g_Bl[512 * IN_F];

// ---------------- helpers ----------------
__device__ __forceinline__ uint32_t smem_u32(const void* p) {
    uint32_t a;
    asm("{ .reg .u64 t; cvta.to.shared.u64 t, %1; cvt.u32.u64 %0, t; }" : "=r"(a) : "l"(p));
    return a;
}
__device__ __forceinline__ void cp16(uint32_t s, const void* g) {
    asm volatile("cp.async.cg.shared.global [%0], [%1], 16;" :: "r"(s), "l"(g));
}
#define CP_COMMIT() asm volatile("cp.async.commit_group;" ::: "memory")
#define CP_WAIT1()  asm volatile("cp.async.wait_group 1;" ::: "memory")
#define CP_WAIT0()  asm volatile("cp.async.wait_group 0;" ::: "memory")

__device__ __forceinline__ void mma_fp16(float* d, const uint32_t* a, const uint32_t* b) {
    asm volatile(
        "mma.sync.aligned.m16n8k16.row.col.f32.f16.f16.f32 "
        "{%0,%1,%2,%3}, {%4,%5,%6,%7}, {%8,%9}, {%0,%1,%2,%3};"
        : "+f"(d[0]), "+f"(d[1]), "+f"(d[2]), "+f"(d[3])
        : "r"(a[0]), "r"(a[1]), "r"(a[2]), "r"(a[3]), "r"(b[0]), "r"(b[1]));
}

// ---------------- zero scratch ----------------
__global__ void zero_kernel() {
    int i = blockIdx.x * blockDim.x + threadIdx.x;
    if (i < N_NODES) { g_counts[i] = 0; g_cursor[i] = 0; }
    if (i < C_OUT)   { g_sum[i] = 0.f; g_sumsq[i] = 0.f; }
}

// ---------------- fp16 conversion ----------------
__global__ void convx_kernel(const float* __restrict__ X) {
    int i = blockIdx.x * blockDim.x + threadIdx.x;
    const int total = N_NODES * IN_F / 4;
    if (i >= total) return;
    float4 v = ((const float4*)X)[i];
    __half h[4] = {__float2half_rn(v.x), __float2half_rn(v.y),
                   __float2half_rn(v.z), __float2half_rn(v.w)};
    ((uint2*)g_Xh)[i] = *(uint2*)h;
}

__global__ void padx_kernel() {
    int i = blockIdx.x * blockDim.x + threadIdx.x;
    const int total = (N_PAD - N_NODES) * IN_F;
    if (i >= total) return;
    g_Xh[N_NODES * IN_F + i] = __float2half_rn(0.f);
}

__global__ void convb_kernel(const float* __restrict__ Wl, const float* __restrict__ Wr) {
    int i = blockIdx.x * blockDim.x + threadIdx.x;   // over 512*256
    if (i >= 512 * IN_F) return;
    int n = i >> 8, k = i & 255;
    const float* W = (n < 256) ? Wl : Wr;
    float v = W[k * 256 + (n & 255)];
    __half h = __float2half_rn(v);
    __half l = __float2half_rn(v - __half2float(h));
    g_Bh[n * IN_F + k] = h;
    g_Bl[n * IN_F + k] = l;
}

// ---------------- mma.sync GEMM: Y[50000,512] = X @ [Wl|Wr] ----------------
// grid(4, 391). fp16 2-term split (Xh*Wh + Xh*Wl), fp32 accum, cp.async depth-2.
// bx<2 -> xl (written fp16 to g_xlh); bx>=2 -> xr (fp32).
#define LDB   40               // padded k-stride (halfs) -> conflict-free LDS
#define TSZ   (128 * LDB)      // one operand tile, elems (5120)
#define BUFSZ (3 * TSZ)        // Ah | Bh | Bl
#define GSMEM (2 * BUFSZ * 2)  // bytes: 61440

__global__ void __launch_bounds__(256) gemm_mma_kernel() {
    extern __shared__ __align__(16) char dsm[];
    __half* sm = (__half*)dsm;
    uint32_t sb = smem_u32(dsm);

    const int tid = threadIdx.x;
    const int wid = tid >> 5, lane = tid & 31;
    const int wm = wid & 3, wn = wid >> 2;          // 4 warps on M, 2 on N
    const int q = lane >> 2, c2 = (lane & 3) * 2;
    const int bx = blockIdx.x, by = blockIdx.y;
    const int rowG = by * 128;

    float acc[2][8][4];
#pragma unroll
    for (int mt = 0; mt < 2; mt++)
#pragma unroll
        for (int nt = 0; nt < 8; nt++)
#pragma unroll
            for (int j = 0; j < 4; j++) acc[mt][nt][j] = 0.f;

    auto prefetch = [&](int c, int b) {
        const int k0 = c * 32;
        const uint32_t base = sb + b * (BUFSZ * 2);
#pragma unroll
        for (int i = 0; i < 2; i++) {
            int idx = tid + i * 256;
            int r = idx >> 2, seg = idx & 3;
            uint32_t off = (r * LDB + seg * 8) * 2;
            long ga = (long)(rowG + r) * IN_F + k0 + seg * 8;
            long gb = (long)(bx * 128 + r) * IN_F + k0 + seg * 8;
            cp16(base + off,               g_Xh + ga);
            cp16(base + TSZ * 2 + off,     g_Bh + gb);
            cp16(base + 2 * TSZ * 2 + off, g_Bl + gb);
        }
        CP_COMMIT();
    };

    prefetch(0, 0);
    for (int c = 0; c < 8; c++) {
        if (c < 7) { prefetch(c + 1, (c + 1) & 1); CP_WAIT1(); }
        else       { CP_WAIT0(); }
        __syncthreads();

        const __half* Ah = sm + (c & 1) * BUFSZ;
        const __half* Bh = Ah + TSZ;
        const __half* Bl = Ah + 2 * TSZ;

#pragma unroll
        for (int ks = 0; ks < 2; ks++) {
            const int kk = ks * 16;
            uint32_t ah[2][4];
#pragma unroll
            for (int mt = 0; mt < 2; mt++) {
                int rb = wm * 32 + mt * 16;
                ah[mt][0] = *(const uint32_t*)(Ah + (rb + q) * LDB + kk + c2);
                ah[mt][1] = *(const uint32_t*)(Ah + (rb + q + 8) * LDB + kk + c2);
                ah[mt][2] = *(const uint32_t*)(Ah + (rb + q) * LDB + kk + c2 + 8);
                ah[mt][3] = *(const uint32_t*)(Ah + (rb + q + 8) * LDB + kk + c2 + 8);
            }
            uint32_t bh[8][2], bl[8][2];
#pragma unroll
            for (int nt = 0; nt < 8; nt++) {
                int nb = wn * 64 + nt * 8;
                bh[nt][0] = *(const uint32_t*)(Bh + (nb + q) * LDB + kk + c2);
                bh[nt][1] = *(const uint32_t*)(Bh + (nb + q) * LDB + kk + c2 + 8);
                bl[nt][0] = *(const uint32_t*)(Bl + (nb + q) * LDB + kk + c2);
                bl[nt][1] = *(const uint32_t*)(Bl + (nb + q) * LDB + kk + c2 + 8);
            }
#pragma unroll
            for (int mt = 0; mt < 2; mt++)
#pragma unroll
                for (int nt = 0; nt < 8; nt++) {
                    mma_fp16(acc[mt][nt], ah[mt], bh[nt]);
                    mma_fp16(acc[mt][nt], ah[mt], bl[nt]);
                }
        }
        __syncthreads();
    }

    const int colBase = (bx & 1) * 128;
    if (bx < 2) {   // xl -> fp16
#pragma unroll
        for (int mt = 0; mt < 2; mt++) {
            int r0 = rowG + wm * 32 + mt * 16 + q;
#pragma unroll
            for (int nt = 0; nt < 8; nt++) {
                int col = colBase + wn * 64 + nt * 8 + c2;
                if (r0 < N_NODES)
                    *(__half2*)(g_xlh + (long)r0 * HC + col) =
                        __floats2half2_rn(acc[mt][nt][0], acc[mt][nt][1]);
                if (r0 + 8 < N_NODES)
                    *(__half2*)(g_xlh + (long)(r0 + 8) * HC + col) =
                        __floats2half2_rn(acc[mt][nt][2], acc[mt][nt][3]);
            }
        }
    } else {        // xr -> fp32
#pragma unroll
        for (int mt = 0; mt < 2; mt++) {
            int r0 = rowG + wm * 32 + mt * 16 + q;
#pragma unroll
            for (int nt = 0; nt < 8; nt++) {
                int col = colBase + wn * 64 + nt * 8 + c2;
                if (r0 < N_NODES)
                    *(float2*)(g_xr + (long)r0 * HC + col) = make_float2(acc[mt][nt][0], acc[mt][nt][1]);
                if (r0 + 8 < N_NODES)
                    *(float2*)(g_xr + (long)(r0 + 8) * HC + col) = make_float2(acc[mt][nt][2], acc[mt][nt][3]);
            }
        }
    }
}

// ---------------- CSR build (dst-sorted) ----------------
__global__ void hist_kernel(const int* __restrict__ E) {
    int i = blockIdx.x * blockDim.x + threadIdx.x;
    if (i >= ET) return;
    int d = (i < E_RAW) ? E[E_RAW + i] : (i - E_RAW);
    atomicAdd(&g_counts[d], 1);
}

__global__ void scan1_kernel() {
    __shared__ int sh[1024];
    int b = blockIdx.x, t = threadIdx.x;
    int i = b * 1024 + t;
    int v = (i < N_NODES) ? g_counts[i] : 0;
    sh[t] = v;
    __syncthreads();
    for (int off = 1; off < 1024; off <<= 1) {
        int add = (t >= off) ? sh[t - off] : 0;
        __syncthreads();
        sh[t] += add;
        __syncthreads();
    }
    if (i < N_NODES) g_offsets[i + 1] = sh[t];
    if (t == 1023) g_bsum[b] = sh[1023];
}

__global__ void scan2_kernel() {
    __shared__ int sh[64];
    int t = threadIdx.x;
    int v = (t < NB_SCAN) ? g_bsum[t] : 0;
    sh[t] = v;
    __syncthreads();
    for (int off = 1; off < 64; off <<= 1) {
        int add = (t >= off) ? sh[t - off] : 0;
        __syncthreads();
        sh[t] += add;
        __syncthreads();
    }
    if (t < NB_SCAN) g_boff[t] = sh[t] - v;
}

__global__ void scan3_kernel() {
    int b = blockIdx.x;
    int i = b * 1024 + threadIdx.x;
    if (i < N_NODES) g_offsets[i + 1] += g_boff[b];
    if (i == 0) g_offsets[0] = 0;
}

__global__ void scatter_kernel(const int* __restrict__ E) {
    int i = blockIdx.x * blockDim.x + threadIdx.x;
    if (i >= ET) return;
    int s, d;
    if (i < E_RAW) { s = E[i]; d = E[E_RAW + i]; }
    else           { s = d = i - E_RAW; }
    int pos = atomicAdd(&g_cursor[d], 1);
    g_src_sorted[g_offsets[d] + pos] = s;
}

// ---------------- attention: one warp per destination node ----------------
// xl gathered as fp16 (one uint4 = the lane's 8 channels). fp32 math.
__device__ __forceinline__ void unpack8(const uint4& u, float* f) {
    float2 a = __half22float2(*(const __half2*)&u.x);
    float2 b = __half22float2(*(const __half2*)&u.y);
    float2 c = __half22float2(*(const __half2*)&u.z);
    float2 d = __half22float2(*(const __half2*)&u.w);
    f[0] = a.x; f[1] = a.y; f[2] = b.x; f[3] = b.y;
    f[4] = c.x; f[5] = c.y; f[6] = d.x; f[7] = d.y;
}

__global__ void attn_kernel(const float* __restrict__ att,
                            const float* __restrict__ bias) {
    __shared__ float bsum[C_OUT];
    __shared__ float bsq[C_OUT];
    int tid = threadIdx.x;
    if (tid < C_OUT) { bsum[tid] = 0.f; bsq[tid] = 0.f; }
    __syncthreads();

    int warp = (blockIdx.x * blockDim.x + tid) >> 5;
    int lane = tid & 31;

    if (warp < N_NODES) {
        int dst = warp;
        const float4* xr4 = ((const float4*)g_xr) + (long)dst * 64 + lane * 2;
        float4 r0 = xr4[0], r1 = xr4[1];
        float xrv[8] = {r0.x, r0.y, r0.z, r0.w, r1.x, r1.y, r1.z, r1.w};
        float4 a0 = ((const float4*)att)[lane * 2];
        float4 a1 = ((const float4*)att)[lane * 2 + 1];
        float attv[8] = {a0.x, a0.y, a0.z, a0.w, a1.x, a1.y, a1.z, a1.w};

        float m = -1e30f, denom = 0.f;
        float acc[8] = {0.f, 0.f, 0.f, 0.f, 0.f, 0.f, 0.f, 0.f};

        const int e0 = g_offsets[dst], e1 = g_offsets[dst + 1];
        int e = e0;
        const int nq = (e1 - e0) >> 2;

        for (int itq = 0; itq < nq; itq++, e += 4) {
            uint4 U[4];
#pragma unroll
            for (int u = 0; u < 4; u++) {
                int s = g_src_sorted[e + u];
                U[u] = *(((const uint4*)(g_xlh + (long)s * HC)) + lane);
            }
            float xl4v[4][8];
            float p[4];
#pragma unroll
            for (int u = 0; u < 4; u++) {
                unpack8(U[u], xl4v[u]);
                float pp = 0.f;
#pragma unroll
                for (int j = 0; j < 8; j++) {
                    float t = xl4v[u][j] + xrv[j];
                    t = (t > 0.f) ? t : NEG_SLOPE * t;
                    pp = fmaf(attv[j], t, pp);
                }
                p[u] = pp;
            }
#pragma unroll
            for (int u = 0; u < 4; u++) p[u] += __shfl_xor_sync(0xffffffffu, p[u], 4);
#pragma unroll
            for (int u = 0; u < 4; u++) p[u] += __shfl_xor_sync(0xffffffffu, p[u], 2);
#pragma unroll
            for (int u = 0; u < 4; u++) p[u] += __shfl_xor_sync(0xffffffffu, p[u], 1);
#pragma unroll
            for (int u = 0; u < 4; u++) {
                float mn = fmaxf(m, p[u]);
                float sc = __expf(m - mn);
                float w  = __expf(p[u] - mn);
                m = mn;
                denom = fmaf(denom, sc, w);
#pragma unroll
                for (int j = 0; j < 8; j++) acc[j] = fmaf(acc[j], sc, w * xl4v[u][j]);
            }
        }
        for (; e < e1; e++) {
            int s = g_src_sorted[e];
            uint4 U = *(((const uint4*)(g_xlh + (long)s * HC)) + lane);
            float xlv[8];
            unpack8(U, xlv);
            float pp = 0.f;
#pragma unroll
            for (int j = 0; j < 8; j++) {
                float t = xlv[j] + xrv[j];
                t = (t > 0.f) ? t : NEG_SLOPE * t;
                pp = fmaf(attv[j], t, pp);
            }
            pp += __shfl_xor_sync(0xffffffffu, pp, 4);
            pp += __shfl_xor_sync(0xffffffffu, pp, 2);
            pp += __shfl_xor_sync(0xffffffffu, pp, 1);
            float mn = fmaxf(m, pp);
            float sc = __expf(m - mn);
            float w  = __expf(pp - mn);
            m = mn;
            denom = fmaf(denom, sc, w);
#pragma unroll
            for (int j = 0; j < 8; j++) acc[j] = fmaf(acc[j], sc, w * xlv[j]);
        }

        float inv = 1.f / (denom + 1e-16f);
        float v[8];
#pragma unroll
        for (int j = 0; j < 8; j++) v[j] = acc[j] * inv;
#pragma unroll
        for (int j = 0; j < 8; j++) {
            v[j] += __shfl_xor_sync(0xffffffffu, v[j], 8);
            v[j] += __shfl_xor_sync(0xffffffffu, v[j], 16);
        }
        if (lane < 8) {
#pragma unroll
            for (int j = 0; j < 8; j++) {
                int c = lane * 8 + j;
                float o = 0.25f * v[j] + bias[c];
                g_out[(long)dst * C_OUT + c] = o;
                atomicAdd(&bsum[c], o);
                atomicAdd(&bsq[c], o * o);
            }
        }
    }
    __syncthreads();
    if (tid < C_OUT) {
        atomicAdd(&g_sum[tid], bsum[tid]);
        atomicAdd(&g_sumsq[tid], bsq[tid]);
    }
}

// ---------------- GraphNorm ----------------
__global__ void finalize_kernel(const float* __restrict__ gw,
                                const float* __restrict__ gms) {
    int c = threadIdx.x;
    const float invN = 1.f / (float)N_NODES;
    float mu  = g_sum[c] * invN;
    float msq = g_sumsq[c] * invN;
    float a   = gms[c];
    float var = msq - 2.f * a * mu * mu + a * a * mu * mu;
    g_scale[c] = gw[c] * rsqrtf(var + 1e-5f);
    g_shift[c] = a * mu;
}

__global__ void norm_kernel(const float* __restrict__ gb,
                            float* __restrict__ out) {
    int i = blockIdx.x * blockDim.x + threadIdx.x;
    const int total = N_NODES * C_OUT / 4;
    if (i >= total) return;
    float4 v = ((const float4*)g_out)[i];
    int c = (i & 15) * 4;
    v.x = g_scale[c + 0] * (v.x - g_shift[c + 0]) + gb[c + 0];
    v.y = g_scale[c + 1] * (v.y - g_shift[c + 1]) + gb[c + 1];
    v.z = g_scale[c + 2] * (v.z - g_shift[c + 2]) + gb[c + 2];
    v.w = g_scale[c + 3] * (v.w - g_shift[c + 3]) + gb[c + 3];
    ((float4*)out)[i] = v;
}

// ---------------- launch ----------------
extern "C" void kernel_launch(void* const* d_in, const int* in_sizes, int n_in,
                              void* d_out, int out_size) {
    const float* X    = (const float*)d_in[0];
    const int*   E    = (const int*)  d_in[1];
    const float* Wl   = (const float*)d_in[2];
    const float* Wr   = (const float*)d_in[3];
    const float* att  = (const float*)d_in[4];
    const float* bias = (const float*)d_in[5];
    const float* gw   = (const float*)d_in[6];
    const float* gb   = (const float*)d_in[7];
    const float* gms  = (const float*)d_in[8];
    float* out = (float*)d_out;

    cudaFuncSetAttribute(gemm_mma_kernel, cudaFuncAttributeMaxDynamicSharedMemorySize, GSMEM);

    zero_kernel<<<(N_NODES + 255) / 256, 256>>>();
    convx_kernel<<<(N_NODES * IN_F / 4 + 255) / 256, 256>>>(X);
    padx_kernel<<<((N_PAD - N_NODES) * IN_F + 255) / 256, 256>>>();
    convb_kernel<<<(512 * IN_F + 255) / 256, 256>>>(Wl, Wr);
    gemm_mma_kernel<<<dim3(4, N_PAD / 128), 256, GSMEM>>>();
    hist_kernel<<<(ET + 255) / 256, 256>>>(E);
    scan1_kernel<<<NB_SCAN, 1024>>>();
    scan2_kernel<<<1, 64>>>();
    scan3_kernel<<<NB_SCAN, 1024>>>();
    scatter_kernel<<<(ET + 255) / 256, 256>>>(E);
    attn_kernel<<<(N_NODES + 7) / 8, 256>>>(att, bias);
    finalize_kernel<<<1, C_OUT>>>(gw, gms);
    norm_kernel<<<(N_NODES * C_OUT / 4 + 255) / 256, 256>>>(gb, out);
}